// round 16
// baseline (speedup 1.0000x reference)
#include <cuda_runtime.h>
#include <math.h>
#include <stdint.h>

#define BSZ   4096
#define QSZ   32768
#define DIM   128
#define QSPLIT 2
#define QPART (QSZ / QSPLIT)   // 16384
#define NBLK  (QSZ / 64)       // 512 column blocks of 64
#define MARGIN 0.01f
#define LG_NSEG  2
#define LG_COLS  (BSZ / LG_NSEG) // 2048

#define INV_T 10.0f
#define SHIFT 10.0f

// ---------------- scratch (static device globals; no allocation) ----------------
__device__ float    g_pn [2][BSZ * DIM];
__device__ uint32_t g_pnh[2][BSZ * DIM / 2];  // p normalized, bf16-hi packed pairs
__device__ uint32_t g_pnm[2][BSZ * DIM / 2];  // bf16-mid
__device__ float    g_nn [2][BSZ * DIM];
__device__ uint32_t g_qh [QSZ * DIM / 2];     // queue bf16-hi packed pairs (8 MB)
__device__ float    g_bmax[2][BSZ][NBLK];     // per-row per-64col-block approx max (16 MB)
__device__ float    g_rowpart[2][LG_NSEG][BSZ];
__device__ float    g_colpart[2][32][BSZ];
__device__ float    g_diag[2][BSZ];

// ---------------- helpers ----------------
__device__ __forceinline__ uint32_t smem_u32(const void* p) {
    uint32_t a;
    asm("{ .reg .u64 t; cvta.to.shared.u64 t, %1; cvt.u32.u64 %0, t; }" : "=r"(a) : "l"(p));
    return a;
}
__device__ __forceinline__ void mma_bf16(float c[4], const uint32_t a[4], const uint32_t b[2]) {
    asm volatile(
        "mma.sync.aligned.m16n8k16.row.col.f32.bf16.bf16.f32 "
        "{%0,%1,%2,%3}, {%4,%5,%6,%7}, {%8,%9}, {%0,%1,%2,%3};\n"
        : "+f"(c[0]), "+f"(c[1]), "+f"(c[2]), "+f"(c[3])
        : "r"(a[0]), "r"(a[1]), "r"(a[2]), "r"(a[3]), "r"(b[0]), "r"(b[1]));
}
__device__ __forceinline__ uint32_t pack_bf16(float lo, float hi_) {
    uint32_t r;
    asm("cvt.rn.bf16x2.f32 %0, %1, %2;" : "=r"(r) : "f"(hi_), "f"(lo));
    return r;
}
__device__ __forceinline__ void split8_bf16(const float* p, uint32_t oh[4], uint32_t om[4]) {
#pragma unroll
    for (int t = 0; t < 4; t++) {
        float f0 = p[2 * t], f1 = p[2 * t + 1];
        uint32_t h = pack_bf16(f0, f1);
        float h0 = __uint_as_float(h << 16);
        float h1 = __uint_as_float(h & 0xffff0000u);
        oh[t] = h;
        om[t] = pack_bf16(f0 - h0, f1 - h1);
    }
}
__device__ __forceinline__ void hi8_bf16(const float* p, uint32_t oh[4]) {
#pragma unroll
    for (int t = 0; t < 4; t++) oh[t] = pack_bf16(p[2 * t], p[2 * t + 1]);
}
__device__ __forceinline__ void cp16(uint32_t dst, const void* src) {
    asm volatile("cp.async.cg.shared.global [%0], [%1], 16;" :: "r"(dst), "l"(src) : "memory");
}
#define CP_COMMIT() asm volatile("cp.async.commit_group;" ::: "memory")
#define CP_WAIT(n)  asm volatile("cp.async.wait_group %0;" :: "n"(n) : "memory")

// ---------------- K0: queue -> bf16-hi packed pairs ----------------
__global__ void k_qsplit(const float* __restrict__ queue) {
    int i = blockIdx.x * blockDim.x + threadIdx.x;
    if (i >= QSZ * DIM / 8) return;
    uint32_t oh[4];
    hi8_bf16(queue + (size_t)i * 8, oh);
#pragma unroll
    for (int t = 0; t < 4; t++) g_qh[(size_t)i * 4 + t] = oh[t];
}

// ---------------- K1: L2 normalize + bf16 hi/mid split (for k_logits) ----------------
__global__ void k_normalize(const float* __restrict__ p1, const float* __restrict__ p2) {
    int gw   = (blockIdx.x * blockDim.x + threadIdx.x) >> 5;
    int lane = threadIdx.x & 31;
    if (gw >= 2 * BSZ) return;
    int input = gw >> 12;
    int row   = gw & (BSZ - 1);
    const float* src = (input ? p2 : p1) + (size_t)row * DIM;
    float4 v = ((const float4*)src)[lane];
    float s = v.x * v.x + v.y * v.y + v.z * v.z + v.w * v.w;
#pragma unroll
    for (int o = 16; o; o >>= 1) s += __shfl_xor_sync(0xffffffff, s, o);
    float inv = rsqrtf(s);
    float4 o4 = make_float4(v.x * inv, v.y * inv, v.z * inv, v.w * inv);
    ((float4*)(g_pn[input] + (size_t)row * DIM))[lane] = o4;
    uint32_t h0 = pack_bf16(o4.x, o4.y);
    uint32_t h1 = pack_bf16(o4.z, o4.w);
    uint32_t m0 = pack_bf16(o4.x - __uint_as_float(h0 << 16),
                            o4.y - __uint_as_float(h0 & 0xffff0000u));
    uint32_t m1 = pack_bf16(o4.z - __uint_as_float(h1 << 16),
                            o4.w - __uint_as_float(h1 & 0xffff0000u));
    ((uint2*)(g_pnh[input] + (size_t)row * 64))[lane] = make_uint2(h0, h1);
    ((uint2*)(g_pnm[input] + (size_t)row * 64))[lane] = make_uint2(m0, m1);
}

// ---------------- shared bf16 engine constants ----------------
#define A_WST   68
#define B_WST   20
#define A_WORDS (128 * A_WST)                   // 8704
#define B_WORDS (256 * B_WST)                   // 5120

// ---------------- K2: 1-term bf16 GEMM + per-64col-block max ----------------
// grid (32, 2, 2), block 256 (8 warps: wm = wid&1, wn = wid>>1). BM=128, BN=256.
#define NN_SMEM_WORDS (A_WORDS + 2 * B_WORDS)
#define NN_SMEM_BYTES (NN_SMEM_WORDS * 4)       // 75,776 B

__global__ void __launch_bounds__(256, 1) k_nn() {
    extern __shared__ uint32_t smw[];
    uint32_t* Ah    = smw;                       // [128][68] words
    uint32_t* Bbase = smw + A_WORDS;             // buf j @ j*B_WORDS (hi only)
    uint32_t sb_B = smem_u32(Bbase);

    const int rb = blockIdx.x, input = blockIdx.y, qseg = blockIdx.z;
    const int tid = threadIdx.x, lane = tid & 31, wid = tid >> 5;
    const int wm = wid & 1, wn = wid >> 1;       // 2 x 4 warp grid
    const int gId = lane >> 2, tig = lane & 3;
    const size_t qbaseW = (size_t)qseg * QPART * (DIM / 2);

    const int NCH = (QPART / 256) * 4;           // 256 chunks (qt 64 x kk 4)

#define NN_COPY(c)                                                              \
    {                                                                           \
        int _qt = (c) >> 2, _klw = ((c) & 3) * 16;                              \
        uint32_t _base = sb_B + (uint32_t)(((c) & 1) * B_WORDS) * 4;            \
        _Pragma("unroll")                                                       \
        for (int _x = 0; _x < 4; _x++) {                                        \
            int _f = tid + _x * 256;                                            \
            int _r = _f >> 2, _q = _f & 3;                                      \
            const uint32_t* _sp = g_qh + qbaseW                                 \
                + (size_t)(_qt * 256 + _r) * (DIM / 2) + _klw + _q * 4;         \
            uint32_t _dst = _base + (uint32_t)(_r * B_WST + _q * 4) * 4;        \
            cp16(_dst, _sp);                                                    \
        }                                                                       \
    }

    NN_COPY(0);
    CP_COMMIT();

    // build bf16-hi A in smem: 2 threads per row
    {
        int row = tid >> 1, half = tid & 1;
        const float* arow = g_pn[input] + ((size_t)rb * 128 + row) * DIM + half * 64;
        uint32_t wbase = row * A_WST + half * 32;
#pragma unroll
        for (int g = 0; g < 8; g++) {
            uint32_t oh[4];
            hi8_bf16(arow + g * 8, oh);
#pragma unroll
            for (int t = 0; t < 4; t++) Ah[wbase + g * 4 + t] = oh[t];
        }
    }

#pragma unroll 1
    for (int qt = 0; qt < QPART / 256; qt++) {
        float c[4][8][4];
#pragma unroll
        for (int ma = 0; ma < 4; ma++)
#pragma unroll
            for (int na = 0; na < 8; na++)
#pragma unroll
                for (int r = 0; r < 4; r++) c[ma][na][r] = 0.f;

#pragma unroll 1
        for (int kk = 0; kk < 4; kk++) {
            int ch = qt * 4 + kk;
            if (ch + 1 < NCH) { NN_COPY(ch + 1); CP_COMMIT(); CP_WAIT(1); }
            else              { CP_WAIT(0); }
            __syncthreads();

            const uint32_t* bh = Bbase + (ch & 1) * B_WORDS;
#pragma unroll
            for (int ka = 0; ka < 2; ka++) {
                int kwB = ka * 8 + tig;
                int kwA = kk * 16 + kwB;
                uint32_t ah[4][4], bhf[8][2];
#pragma unroll
                for (int ma = 0; ma < 4; ma++) {
                    int rowA = wm * 64 + ma * 16 + gId;
                    ah[ma][0] = Ah[rowA * A_WST + kwA];
                    ah[ma][1] = Ah[(rowA + 8) * A_WST + kwA];
                    ah[ma][2] = Ah[rowA * A_WST + kwA + 4];
                    ah[ma][3] = Ah[(rowA + 8) * A_WST + kwA + 4];
                }
#pragma unroll
                for (int na = 0; na < 8; na++) {
                    int colB = wn * 64 + na * 8 + gId;
                    bhf[na][0] = bh[colB * B_WST + kwB];
                    bhf[na][1] = bh[colB * B_WST + kwB + 4];
                }
#pragma unroll
                for (int ma = 0; ma < 4; ma++)
#pragma unroll
                    for (int na = 0; na < 8; na++)
                        mma_bf16(c[ma][na], ah[ma], bhf[na]);
            }
            __syncthreads();
        }

        // per-row block max over this warp's 64 cols -> g_bmax
        float sl[8];
#pragma unroll
        for (int s = 0; s < 8; s++) sl[s] = -3.4e38f;
#pragma unroll
        for (int ma = 0; ma < 4; ma++)
#pragma unroll
            for (int na = 0; na < 8; na++)
#pragma unroll
                for (int r = 0; r < 4; r++) {
                    int s = ma * 2 + (r >> 1);
                    if (c[ma][na][r] > sl[s]) sl[s] = c[ma][na][r];
                }
        int gb = qseg * 256 + qt * 4 + wn;
#pragma unroll
        for (int s = 0; s < 8; s++) {
            float v = sl[s];
            v = fmaxf(v, __shfl_xor_sync(0xffffffff, v, 1));
            v = fmaxf(v, __shfl_xor_sync(0xffffffff, v, 2));
            if (tig == 0) {
                int row = rb * 128 + wm * 64 + (s >> 1) * 16 + gId + ((s & 1) ? 8 : 0);
                g_bmax[input][row][gb] = v;
            }
        }
    }
}

// ---------------- K3: margin filter + EXACT fp32 rescore + gather ----------------
// One warp per (input,row). Two streaming passes over g_bmax (no register cache);
// 4 independent accumulators per column dot (chain 128 -> 32 dependent FFMA).
__global__ void k_rescore(const float* __restrict__ queue) {
    __shared__ float4 sp4[8][32];
    int gw   = (blockIdx.x * blockDim.x + threadIdx.x) >> 5;
    int lane = threadIdx.x & 31;
    if (gw >= 2 * BSZ) return;
    int input = gw >> 12, row = gw & (BSZ - 1);
    int w = (threadIdx.x >> 5);
    const float* bmrow = g_bmax[input][row];

    float4 p = ((const float4*)(g_pn[input] + (size_t)row * DIM))[lane];
    sp4[w][lane] = p;
    __syncwarp();

    // pass 1: global max (streaming, no cache)
    float mx = -3.4e38f;
#pragma unroll
    for (int i = 0; i < 16; i++) mx = fmaxf(mx, bmrow[lane + 32 * i]);
#pragma unroll
    for (int o = 16; o; o >>= 1) mx = fmaxf(mx, __shfl_xor_sync(0xffffffff, mx, o));
    float thr = mx - MARGIN;

    float bestv = -3.4e38f;
    int   besti = 0x7fffffff;
    // pass 2: ballot + exact rescore of candidate blocks
#pragma unroll 1
    for (int i = 0; i < 16; i++) {
        unsigned msk = __ballot_sync(0xffffffff, bmrow[lane + 32 * i] >= thr);
        while (msk) {
            int b = __ffs(msk) - 1;
            msk &= msk - 1;
            int colbase = (b + 32 * i) * 64;
#pragma unroll 1
            for (int cc = 0; cc < 2; cc++) {
                int col = colbase + lane + cc * 32;
                const float4* q4 = (const float4*)(queue + (size_t)col * DIM);
                float d0 = 0.f, d1 = 0.f, d2 = 0.f, d3 = 0.f;
#pragma unroll
                for (int j = 0; j < 8; j++) {
                    float4 qa = q4[j * 4 + 0], pa = sp4[w][j * 4 + 0];
                    float4 qb = q4[j * 4 + 1], pb = sp4[w][j * 4 + 1];
                    float4 qc = q4[j * 4 + 2], pc = sp4[w][j * 4 + 2];
                    float4 qd = q4[j * 4 + 3], pd = sp4[w][j * 4 + 3];
                    d0 += qa.x * pa.x + qa.y * pa.y + qa.z * pa.z + qa.w * pa.w;
                    d1 += qb.x * pb.x + qb.y * pb.y + qb.z * pb.z + qb.w * pb.w;
                    d2 += qc.x * pc.x + qc.y * pc.y + qc.z * pc.z + qc.w * pc.w;
                    d3 += qd.x * pd.x + qd.y * pd.y + qd.z * pd.z + qd.w * pd.w;
                }
                float d = (d0 + d1) + (d2 + d3);
                if (d > bestv || (d == bestv && col < besti)) { bestv = d; besti = col; }
            }
        }
    }
    // warp reduce (max, min-index tie)
#pragma unroll
    for (int o = 16; o; o >>= 1) {
        float ov = __shfl_xor_sync(0xffffffff, bestv, o);
        int   oi = __shfl_xor_sync(0xffffffff, besti, o);
        if (ov > bestv || (ov == bestv && oi < besti)) { bestv = ov; besti = oi; }
    }
    float4 qv = ((const float4*)(queue + (size_t)besti * DIM))[lane];
    ((float4*)(g_nn[input] + (size_t)row * DIM))[lane] = qv;
}

// ---------------- K4: logits via 3-term bf16 engine + fixed-shift exp partial sums ----------------
#define BPAIRW (2 * B_WORDS)
#define LG_SMEM_WORDS (2 * A_WORDS + 2 * BPAIRW + 256 + 512)
#define LG_SMEM_BYTES (LG_SMEM_WORDS * 4)

__global__ void __launch_bounds__(256, 1) k_logits() {
    extern __shared__ uint32_t smv[];
    uint32_t* Ah    = smv;                       // [128][68]
    uint32_t* Am    = smv + A_WORDS;
    uint32_t* Bbase = smv + 2 * A_WORDS;
    float*    scol  = (float*)(Bbase + 2 * BPAIRW);  // [256]
    float*    srow  = scol + 256;                     // [128][4]
    uint32_t sb_B = smem_u32(Bbase);

    const int rb = blockIdx.x, m = blockIdx.y, nseg = blockIdx.z;
    const int colbase = nseg * LG_COLS;
    const int tid = threadIdx.x, lane = tid & 31, wid = tid >> 5;
    const int wm = wid & 1, wn = wid >> 1;
    const int gId = lane >> 2, tig = lane & 3;
    const uint32_t* Bh = g_pnh[1 - m];
    const uint32_t* Bm_ = g_pnm[1 - m];

    const int LNCH = (LG_COLS / 256) * 4;        // 32 chunks

#define LG_COPY(c)                                                              \
    {                                                                           \
        int _qt = (c) >> 2, _klw = ((c) & 3) * 16;                              \
        uint32_t _base = sb_B + (uint32_t)(((c) & 1) * BPAIRW) * 4;             \
        _Pragma("unroll")                                                       \
        for (int _x = 0; _x < 8; _x++) {                                        \
            int _f = tid + _x * 256;                                            \
            int _arr = _f >> 10, _rem = _f & 1023;                              \
            int _r = _rem >> 2, _q = _rem & 3;                                  \
            const uint32_t* _sp = (_arr ? Bm_ : Bh)                             \
                + (size_t)(colbase + _qt * 256 + _r) * (DIM / 2) + _klw + _q * 4; \
            uint32_t _dst = _base + (uint32_t)(_arr * B_WORDS + _r * B_WST + _q * 4) * 4; \
            cp16(_dst, _sp);                                                    \
        }                                                                       \
    }

    LG_COPY(0);
    CP_COMMIT();

    {
        int row = tid >> 1, half = tid & 1;
        const float* arow = g_nn[m] + ((size_t)rb * 128 + row) * DIM + half * 64;
        uint32_t wbase = row * A_WST + half * 32;
#pragma unroll
        for (int g = 0; g < 8; g++) {
            uint32_t oh[4], om[4];
            split8_bf16(arow + g * 8, oh, om);
#pragma unroll
            for (int t = 0; t < 4; t++) {
                Ah[wbase + g * 4 + t] = oh[t];
                Am[wbase + g * 4 + t] = om[t];
            }
        }
    }
    scol[tid] = 0.f;

    float rs[8];
#pragma unroll
    for (int s = 0; s < 8; s++) rs[s] = 0.f;

#pragma unroll 1
    for (int qt = 0; qt < LG_COLS / 256; qt++) {
        float c[4][8][4];
#pragma unroll
        for (int ma = 0; ma < 4; ma++)
#pragma unroll
            for (int na = 0; na < 8; na++)
#pragma unroll
                for (int r = 0; r < 4; r++) c[ma][na][r] = 0.f;

#pragma unroll 1
        for (int kk = 0; kk < 4; kk++) {
            int ch = qt * 4 + kk;
            if (ch + 1 < LNCH) { LG_COPY(ch + 1); CP_COMMIT(); CP_WAIT(1); }
            else               { CP_WAIT(0); }
            __syncthreads();

            const uint32_t* bh = Bbase + (ch & 1) * BPAIRW;
            const uint32_t* bm = bh + B_WORDS;
#pragma unroll
            for (int ka = 0; ka < 2; ka++) {
                int kwB = ka * 8 + tig;
                int kwA = kk * 16 + kwB;
                uint32_t ah[4][4], am[4][4], bhf[8][2], bmf[8][2];
#pragma unroll
                for (int ma = 0; ma < 4; ma++) {
                    int rowA = wm * 64 + ma * 16 + gId;
                    ah[ma][0] = Ah[rowA * A_WST + kwA];
                    ah[ma][1] = Ah[(rowA + 8) * A_WST + kwA];
                    ah[ma][2] = Ah[rowA * A_WST + kwA + 4];
                    ah[ma][3] = Ah[(rowA + 8) * A_WST + kwA + 4];
                    am[ma][0] = Am[rowA * A_WST + kwA];
                    am[ma][1] = Am[(rowA + 8) * A_WST + kwA];
                    am[ma][2] = Am[rowA * A_WST + kwA + 4];
                    am[ma][3] = Am[(rowA + 8) * A_WST + kwA + 4];
                }
#pragma unroll
                for (int na = 0; na < 8; na++) {
                    int colB = wn * 64 + na * 8 + gId;
                    bhf[na][0] = bh[colB * B_WST + kwB];
                    bhf[na][1] = bh[colB * B_WST + kwB + 4];
                    bmf[na][0] = bm[colB * B_WST + kwB];
                    bmf[na][1] = bm[colB * B_WST + kwB + 4];
                }
#pragma unroll
                for (int ma = 0; ma < 4; ma++)
#pragma unroll
                    for (int na = 0; na < 8; na++)
                        mma_bf16(c[ma][na], ah[ma], bhf[na]);
#pragma unroll
                for (int ma = 0; ma < 4; ma++)
#pragma unroll
                    for (int na = 0; na < 8; na++)
                        mma_bf16(c[ma][na], ah[ma], bmf[na]);
#pragma unroll
                for (int ma = 0; ma < 4; ma++)
#pragma unroll
                    for (int na = 0; na < 8; na++)
                        mma_bf16(c[ma][na], am[ma], bhf[na]);
            }
            __syncthreads();
        }

        float ctmp[8][2];
#pragma unroll
        for (int na = 0; na < 8; na++) { ctmp[na][0] = 0.f; ctmp[na][1] = 0.f; }
        int gcol0 = colbase + qt * 256 + wn * 64;
#pragma unroll
        for (int ma = 0; ma < 4; ma++) {
#pragma unroll
            for (int na = 0; na < 8; na++) {
#pragma unroll
                for (int r = 0; r < 4; r++) {
                    float l = c[ma][na][r] * INV_T;
                    float e = __expf(l - SHIFT);
                    rs[ma * 2 + (r >> 1)] += e;
                    ctmp[na][r & 1] += e;
                    int grow = rb * 128 + wm * 64 + ma * 16 + gId + (r >> 1) * 8;
                    int gcol = gcol0 + na * 8 + 2 * tig + (r & 1);
                    if (gcol == grow) g_diag[m][grow] = l;
                }
            }
        }
#pragma unroll
        for (int na = 0; na < 8; na++)
#pragma unroll
            for (int r = 0; r < 2; r++) {
#pragma unroll
                for (int off = 4; off <= 16; off <<= 1)
                    ctmp[na][r] += __shfl_xor_sync(0xffffffff, ctmp[na][r], off);
            }
        if (gId == 0) {
#pragma unroll
            for (int na = 0; na < 8; na++) {
                atomicAdd(&scol[wn * 64 + na * 8 + 2 * tig + 0], ctmp[na][0]);
                atomicAdd(&scol[wn * 64 + na * 8 + 2 * tig + 1], ctmp[na][1]);
            }
        }
        __syncthreads();
        g_colpart[m][rb][colbase + qt * 256 + tid] = scol[tid];
        scol[tid] = 0.f;
    }

#pragma unroll
    for (int s = 0; s < 8; s++) {
#pragma unroll
        for (int off = 1; off <= 2; off <<= 1)
            rs[s] += __shfl_xor_sync(0xffffffff, rs[s], off);
        if (tig == 0) {
            int row = wm * 64 + (s >> 1) * 16 + gId + ((s & 1) ? 8 : 0);
            srow[row * 4 + wn] = rs[s];
        }
    }
    __syncthreads();
    if (tid < 128)
        g_rowpart[m][nseg][rb * 128 + tid] =
            srow[tid * 4] + srow[tid * 4 + 1] + srow[tid * 4 + 2] + srow[tid * 4 + 3];
}

// ---------------- K5: final losses from partials ----------------
__global__ void k_loss(float* __restrict__ out) {
    int g = blockIdx.x * blockDim.x + threadIdx.x;
    if (g >= 2 * BSZ) return;
    int m = g >> 12, i = g & (BSZ - 1);
    float rsum = 0.f, csum = 0.f;
#pragma unroll
    for (int s = 0; s < LG_NSEG; s++) rsum += g_rowpart[m][s][i];
#pragma unroll 8
    for (int rb = 0; rb < 32; rb++) csum += g_colpart[m][rb][i];
    float d = g_diag[m][i];
    out[(size_t)(2 * m) * BSZ + i]     = SHIFT + logf(rsum) - d;
    out[(size_t)(2 * m + 1) * BSZ + i] = SHIFT + logf(csum) - d;
}

// ---------------- launch ----------------
extern "C" void kernel_launch(void* const* d_in, const int* in_sizes, int n_in,
                              void* d_out, int out_size) {
    const float *p1 = nullptr, *p2 = nullptr, *queue = nullptr;
    for (int i = 0; i < n_in; i++) {
        if (in_sizes[i] == QSZ * DIM) queue = (const float*)d_in[i];
        else if (!p1) p1 = (const float*)d_in[i];
        else p2 = (const float*)d_in[i];
    }
    float* out = (float*)d_out;

    cudaFuncSetAttribute(k_nn, cudaFuncAttributeMaxDynamicSharedMemorySize, NN_SMEM_BYTES);
    cudaFuncSetAttribute(k_logits, cudaFuncAttributeMaxDynamicSharedMemorySize, LG_SMEM_BYTES);

    k_normalize<<<(2 * BSZ * 32 + 255) / 256, 256>>>(p1, p2);
    k_qsplit<<<(QSZ * DIM / 8 + 255) / 256, 256>>>(queue);

    dim3 g2(BSZ / 128, 2, QSPLIT);
    k_nn<<<g2, 256, NN_SMEM_BYTES>>>();

    k_rescore<<<(2 * BSZ * 32 + 255) / 256, 256>>>(queue);

    dim3 g4(BSZ / 128, 2, LG_NSEG);
    k_logits<<<g4, 256, LG_SMEM_BYTES>>>();

    k_loss<<<(2 * BSZ + 255) / 256, 256>>>(out);
}